// round 13
// baseline (speedup 1.0000x reference)
#include <cuda_runtime.h>
#include <cuda_bf16.h>
#include <cuda_fp16.h>
#include <cstdint>

typedef unsigned long long ull;

// Problem constants (fixed shapes)
#define BB   64
#define TT   256
#define VV   10000
#define VPAD 10240
#define EE   100
#define HH   128
#define GG   512          // 4H
#define BT   (BB*TT)      // 16384
#define KSPLIT 256        // A: [h_hi | h_lo] fp16
#define WKS   128         // B: W_fc fp16 (single copy; shared by hi & lo MMAs)

#define LOGITS_ELEMS ((size_t)BT * VV)          // 163,840,000
#define HF_OFF  LOGITS_ELEMS
#define CF_OFF  (LOGITS_ELEMS + (size_t)BB*HH)
#define FULL_OUT (LOGITS_ELEMS + 2ull*BB*HH)

// Scratch (device globals; allocation-free per harness rules)
__device__ float  g_xproj[(size_t)BT * GG];          // 33.5 MB
__device__ __half g_hs_split[(size_t)BT * KSPLIT];   // 8.4 MB  [bt][hi|lo]
__device__ __half g_wfc_split[(size_t)VPAD * WKS];   // 2.6 MB  [v][hi]

// ---------------------------------------------------------------------------
// Helpers
// ---------------------------------------------------------------------------
__device__ __forceinline__ uint32_t smem_u32(const void* p) {
    uint32_t a;
    asm("{ .reg .u64 t; cvta.to.shared.u64 t, %1; cvt.u32.u64 %0, t; }" : "=r"(a) : "l"(p));
    return a;
}
__device__ __forceinline__ void cp16(uint32_t dst, const void* src) {
    asm volatile("cp.async.cg.shared.global [%0], [%1], 16;" :: "r"(dst), "l"(src));
}
#define CP_COMMIT() asm volatile("cp.async.commit_group;" ::: "memory")
#define CP_WAIT(n)  asm volatile("cp.async.wait_group %0;" :: "n"(n) : "memory")

__device__ __forceinline__ void ldm4(uint32_t* r, uint32_t addr) {
    asm volatile("ldmatrix.sync.aligned.m8n8.x4.shared.b16 {%0,%1,%2,%3}, [%4];"
                 : "=r"(r[0]), "=r"(r[1]), "=r"(r[2]), "=r"(r[3]) : "r"(addr));
}
__device__ __forceinline__ void mma16816(float* c, const uint32_t* a,
                                         uint32_t b0, uint32_t b1) {
    asm volatile(
        "mma.sync.aligned.m16n8k16.row.col.f32.f16.f16.f32 "
        "{%0,%1,%2,%3}, {%4,%5,%6,%7}, {%8,%9}, {%0,%1,%2,%3};"
        : "+f"(c[0]), "+f"(c[1]), "+f"(c[2]), "+f"(c[3])
        : "r"(a[0]), "r"(a[1]), "r"(a[2]), "r"(a[3]), "r"(b0), "r"(b1));
}
__device__ __forceinline__ ull fma2_(ull a, ull b, ull c) {
    ull d;
    asm("fma.rn.f32x2 %0, %1, %2, %3;" : "=l"(d) : "l"(a), "l"(b), "l"(c));
    return d;
}
__device__ __forceinline__ void unpack2_(ull v, float& x, float& y) {
    asm("mov.b64 {%0, %1}, %2;" : "=f"(x), "=f"(y) : "l"(v));
}

// Fast, saturation-safe activations (MUFU EX2 based)
__device__ __forceinline__ float sigm_fast(float x) {
    return 1.f / (1.f + __expf(-x));
}
__device__ __forceinline__ float tanh_fast(float x) {
    return 2.f / (1.f + __expf(-2.f * x)) - 1.f;
}

// ---------------------------------------------------------------------------
// Kernel 1: embedding gather + input projection.
// 256 threads, each owns TWO gate rows (g, g+256).
// ---------------------------------------------------------------------------
__global__ __launch_bounds__(256) void k_embed_proj(
    const int* __restrict__ x, const float* __restrict__ emb,
    const float* __restrict__ W_ih, const float* __restrict__ b_ih,
    const float* __restrict__ b_hh)
{
    __shared__ float4 xe_s[16][25];          // 16 rows x 100 floats
    __shared__ int    toks[16];
    const int bt0 = blockIdx.x * 16;
    const int tid = threadIdx.x;

    if (tid < 16) toks[tid] = x[bt0 + tid];
    __syncthreads();
    for (int i = tid; i < 16 * 25; i += 256) {
        int r = i / 25, e4 = i - r * 25;
        xe_s[r][e4] = *reinterpret_cast<const float4*>(emb + (size_t)toks[r] * EE + 4 * e4);
    }
    __syncthreads();

    const int g0 = tid;
    const int g1 = tid + 256;
    float acc0[16], acc1[16];
#pragma unroll
    for (int r = 0; r < 16; r++) { acc0[r] = 0.f; acc1[r] = 0.f; }

    const float4* W0 = reinterpret_cast<const float4*>(W_ih + (size_t)g0 * EE);
    const float4* W1 = reinterpret_cast<const float4*>(W_ih + (size_t)g1 * EE);
    float4 w0 = W0[0], w1 = W1[0];

    for (int e4 = 0; e4 < 25; e4++) {
        const float4 w0c = w0, w1c = w1;
        if (e4 + 1 < 25) { w0 = W0[e4 + 1]; w1 = W1[e4 + 1]; }   // prefetch
#pragma unroll
        for (int r = 0; r < 16; r++) {
            const float4 v = xe_s[r][e4];    // LDS.128 broadcast
            acc0[r] += w0c.x * v.x; acc1[r] += w1c.x * v.x;
            acc0[r] += w0c.y * v.y; acc1[r] += w1c.y * v.y;
            acc0[r] += w0c.z * v.z; acc1[r] += w1c.z * v.z;
            acc0[r] += w0c.w * v.w; acc1[r] += w1c.w * v.w;
        }
    }
    const float bias0 = b_ih[g0] + b_hh[g0];
    const float bias1 = b_ih[g1] + b_hh[g1];
#pragma unroll
    for (int r = 0; r < 16; r++) {
        g_xproj[(size_t)(bt0 + r) * GG + g0] = acc0[r] + bias0;
        g_xproj[(size_t)(bt0 + r) * GG + g1] = acc1[r] + bias1;
    }
}

// ---------------------------------------------------------------------------
// Kernel 2: LSTM recurrence, ONE barrier per step.
// Thread map: q = tid&3 (gate i/f/g/o), j = tid>>2 (hidden unit); gate row
// = q*128+j. The 4 gates of unit j sit in 4 adjacent lanes of one warp ->
// combine via 3x shfl_xor, no gates smem, no second barrier.
// h double-buffered: step t reads h_s[t&1], writes h_s[(t+1)&1], 1 barrier.
// W k=0..95 in regs (f32x2 pairs), k=96..127 in SMEM pair-quads.
// ---------------------------------------------------------------------------
#define KREG  96
#define SMEM2_BYTES (8*512*16 + 2*HH*4)

__global__ __launch_bounds__(512, 1) void k_lstm(
    const float* __restrict__ W_hh, float* __restrict__ out, long long out_size)
{
    extern __shared__ char smem2raw[];
    ulonglong2* Wt4_s = reinterpret_cast<ulonglong2*>(smem2raw);        // [8][512]
    float*      h_s0  = reinterpret_cast<float*>(smem2raw + 8*512*16);  // [128]
    float*      h_s1  = h_s0 + HH;                                      // [128]

    const int b   = blockIdx.x;
    const int tid = threadIdx.x;
    const int q   = tid & 3;                // gate: 0=i 1=f 2=g 3=o
    const int j   = tid >> 2;               // hidden unit 0..127
    const int row = q * HH + j;             // W_hh / gate row 0..511

    ull wr2[KREG / 2];
    {
        const ulonglong2* Wg = reinterpret_cast<const ulonglong2*>(W_hh + (size_t)row * HH);
#pragma unroll
        for (int i = 0; i < KREG / 4; i++) {
            ulonglong2 u = Wg[i];
            wr2[2 * i]     = u.x;
            wr2[2 * i + 1] = u.y;
        }
    }
    for (int idx = tid; idx < 8 * 512; idx += 512) {
        int jj = idx >> 9;
        int g2 = idx & 511;
        float4 w4 = *reinterpret_cast<const float4*>(W_hh + (size_t)g2 * HH + KREG + 4 * jj);
        Wt4_s[idx] = *reinterpret_cast<ulonglong2*>(&w4);
    }
    float c = 0.f;                           // replicated across the 4 gate lanes
    if (tid < HH) { h_s0[tid] = 0.f; h_s1[tid] = 0.f; }
    __syncthreads();

    const float* xp = g_xproj + (size_t)b * TT * GG;
    float xnext = xp[row];                   // prefetch t=0
    float hlast = 0.f;

    for (int t = 0; t < TT; t++) {
        const float* hbuf = (t & 1) ? h_s1 : h_s0;
        float*       hnew = (t & 1) ? h_s0 : h_s1;
        const ulonglong2* h2q = reinterpret_cast<const ulonglong2*>(hbuf);

        const float accx = xnext;
        if (t + 1 < TT) xnext = __ldg(xp + (t + 1) * GG + row);

        ull acc2a = 0ull, acc2b = 0ull;
#pragma unroll
        for (int k4 = 0; k4 < KREG / 4; k4++) {
            ulonglong2 hp = h2q[k4];         // LDS.128 broadcast
            acc2a = fma2_(wr2[2 * k4],     hp.x, acc2a);
            acc2b = fma2_(wr2[2 * k4 + 1], hp.y, acc2b);
        }
#pragma unroll
        for (int jj = 0; jj < 8; jj++) {
            ulonglong2 hp = h2q[KREG / 4 + jj];
            ulonglong2 wv = Wt4_s[(jj << 9) + row];
            acc2a = fma2_(wv.x, hp.x, acc2a);
            acc2b = fma2_(wv.y, hp.y, acc2b);
        }
        float l0, h0, l1, h1;
        unpack2_(acc2a, l0, h0);
        unpack2_(acc2b, l1, h1);
        const float gv = accx + ((l0 + l1) + (h0 + h1));

        const float v  = (q == 2) ? tanh_fast(gv) : sigm_fast(gv);
        const float a1 = __shfl_xor_sync(0xFFFFFFFFu, v, 1);
        const float a2 = __shfl_xor_sync(0xFFFFFFFFu, v, 2);
        const float a3 = __shfl_xor_sync(0xFFFFFFFFu, v, 3);
        const float ig = (q == 0) ? v  : (q == 1) ? a1 : (q == 2) ? a2 : a3;
        const float fg = (q == 0) ? a1 : (q == 1) ? v  : (q == 2) ? a3 : a2;
        const float gg = (q == 0) ? a2 : (q == 1) ? a3 : (q == 2) ? v  : a1;
        const float og = (q == 0) ? a3 : (q == 1) ? a2 : (q == 2) ? a1 : v;

        c = fg * c + ig * gg;
        const float h = og * tanh_fast(c);
        hlast = h;

        if (q == 0) {
            hnew[j] = h;
            __half hh = __float2half_rn(h);
            float  hl = h - __half2float(hh);
            size_t base = ((size_t)b * TT + t) * KSPLIT;
            g_hs_split[base + j]       = hh;
            g_hs_split[base + 128 + j] = __float2half_rn(hl);
        }
        __syncthreads();                     // hnew visible; nobody runs ahead
    }

    if (q == 0 && out_size >= (long long)FULL_OUT) {
        out[HF_OFF + (size_t)b * HH + j] = hlast;
        out[CF_OFF + (size_t)b * HH + j] = c;
    }
}

// ---------------------------------------------------------------------------
// Kernel 2b: W_fc -> fp16, single copy, zero-padded to VPAD rows
// ---------------------------------------------------------------------------
__global__ __launch_bounds__(256) void k_split_wfc(const float* __restrict__ W_fc)
{
    size_t i = (size_t)blockIdx.x * 256 + threadIdx.x;   // over VPAD*128
    int v = (int)(i >> 7);
    float w = (v < VV) ? W_fc[i] : 0.f;
    g_wfc_split[i] = __float2half_rn(w);
}

// ---------------------------------------------------------------------------
// Kernel 3: logits GEMM via mma.sync. fp16 2-term with shared B, full-K
// resident (96KB), single barrier. 8 warps as 2(m) x 4(n); warp tile 64x32.
// ---------------------------------------------------------------------------
#define SMEM3_BYTES (96 * 1024)

__global__ __launch_bounds__(256, 2) void k_logits_mma(
    const float* __restrict__ b_fc, float* __restrict__ out)
{
    extern __shared__ char smem3[];
    const uint32_t smem_base = smem_u32(smem3);
    const int tid = threadIdx.x;
    const int wid = tid >> 5;
    const int l   = tid & 31;
    const int v0  = blockIdx.x * 128;
    const int bt0 = blockIdx.y * 128;

    const __half* asrc = g_hs_split + (size_t)bt0 * KSPLIT;
    const __half* bsrc = g_wfc_split + (size_t)v0 * WKS;

    const int AHI = 0, ALO = 32768, BBF = 65536;

#pragma unroll
    for (int it = 0; it < 8; it++) {
        int i = tid + it * 256;              // 0..2047
        int row = i >> 4;
        int j   = i & 15;
        uint32_t off = (uint32_t)row * 256 + ((j >> 3) << 7) + (((j & 7) ^ (row & 7)) << 4);
        cp16(smem_base + AHI + off, asrc + (size_t)row * KSPLIT + j * 8);
        cp16(smem_base + ALO + off, asrc + (size_t)row * KSPLIT + 128 + j * 8);
        cp16(smem_base + BBF + off, bsrc + (size_t)row * WKS + j * 8);
    }
    CP_COMMIT();

    const int wm = (wid >> 2) * 64;   // warp m offset (0/64)
    const int wn = (wid & 3) * 32;    // warp n offset (0..96)

    float c[4][4][4];
#pragma unroll
    for (int mi = 0; mi < 4; mi++)
#pragma unroll
        for (int nj = 0; nj < 4; nj++)
#pragma unroll
            for (int qq = 0; qq < 4; qq++) c[mi][nj][qq] = 0.f;

    const int lrow = l & 15;
    const int lsel = l >> 4;

    CP_WAIT(0);
    __syncthreads();                  // only barrier in the whole kernel

#pragma unroll
    for (int k16 = 0; k16 < 8; k16++) {
        const int jj = 2 * k16 + lsel;               // 0..15
        const uint32_t joff = ((jj >> 3) << 7) + (((jj & 7) ^ (lrow & 7)) << 4);

        uint32_t bfr[2][4];
#pragma unroll
        for (int njp = 0; njp < 2; njp++) {
            int r = wn + njp * 16 + lrow;
            ldm4(bfr[njp], smem_base + BBF + (uint32_t)r * 256 + joff);
        }
        uint32_t a[4][4];
#pragma unroll
        for (int mi = 0; mi < 4; mi++) {
            int r = wm + mi * 16 + lrow;
            ldm4(a[mi], smem_base + AHI + (uint32_t)r * 256 + joff);
        }
#pragma unroll
        for (int mi = 0; mi < 4; mi++) {
#pragma unroll
            for (int njp = 0; njp < 2; njp++) {
                mma16816(c[mi][njp * 2 + 0], a[mi], bfr[njp][0], bfr[njp][2]);
                mma16816(c[mi][njp * 2 + 1], a[mi], bfr[njp][1], bfr[njp][3]);
            }
        }
        uint32_t alo[4][4];
#pragma unroll
        for (int mi = 0; mi < 4; mi++) {
            int r = wm + mi * 16 + lrow;
            ldm4(alo[mi], smem_base + ALO + (uint32_t)r * 256 + joff);
        }
#pragma unroll
        for (int mi = 0; mi < 4; mi++) {
#pragma unroll
            for (int njp = 0; njp < 2; njp++) {
                mma16816(c[mi][njp * 2 + 0], alo[mi], bfr[njp][0], bfr[njp][2]);
                mma16816(c[mi][njp * 2 + 1], alo[mi], bfr[njp][1], bfr[njp][3]);
            }
        }
    }

    // Epilogue: bias + guarded float2 stores
    const int g  = l >> 2;
    const int qq = l & 3;
    const int mB = bt0 + wm;
    const int nB = v0 + wn;

#pragma unroll
    for (int nj = 0; nj < 4; nj++) {
        const int v = nB + nj * 8 + 2 * qq;
        if (v >= VV) continue;
        const float2 bias = *reinterpret_cast<const float2*>(b_fc + v);
#pragma unroll
        for (int mi = 0; mi < 4; mi++) {
            const float* cc = c[mi][nj];
            const int r0 = mB + mi * 16 + g;
            float2 o0 = make_float2(cc[0] + bias.x, cc[1] + bias.y);
            float2 o1 = make_float2(cc[2] + bias.x, cc[3] + bias.y);
            *reinterpret_cast<float2*>(out + (size_t)r0 * VV + v)       = o0;
            *reinterpret_cast<float2*>(out + (size_t)(r0 + 8) * VV + v) = o1;
        }
    }
}

// ---------------------------------------------------------------------------
extern "C" void kernel_launch(void* const* d_in, const int* in_sizes, int n_in,
                              void* d_out, int out_size)
{
    const int*   x    = (const int*)  d_in[0];
    const float* emb  = (const float*)d_in[1];
    const float* W_ih = (const float*)d_in[2];
    const float* W_hh = (const float*)d_in[3];
    const float* b_ih = (const float*)d_in[4];
    const float* b_hh = (const float*)d_in[5];
    const float* W_fc = (const float*)d_in[6];
    const float* b_fc = (const float*)d_in[7];
    float* out = (float*)d_out;

    cudaFuncSetAttribute(k_lstm,       cudaFuncAttributeMaxDynamicSharedMemorySize, SMEM2_BYTES);
    cudaFuncSetAttribute(k_logits_mma, cudaFuncAttributeMaxDynamicSharedMemorySize, SMEM3_BYTES);

    // 1) embedding + input projection
    k_embed_proj<<<BT / 16, 256>>>(x, emb, W_ih, b_ih, b_hh);

    // 1b) W_fc fp16 prep (independent of 1/2)
    k_split_wfc<<<(VPAD * WKS) / 256, 256>>>(W_fc);

    // 2) recurrence (writes hs split + h_n/c_n tail of out)
    k_lstm<<<BB, 512, SMEM2_BYTES>>>(W_hh, out, (long long)out_size);

    // 3) logits GEMM on HMMA tensor cores
    dim3 g3(VPAD / 128, BT / 128);
    k_logits_mma<<<g3, 256, SMEM3_BYTES>>>(b_fc, out);
}

// round 14
// speedup vs baseline: 1.3120x; 1.3120x over previous
#include <cuda_runtime.h>
#include <cuda_bf16.h>
#include <cuda_fp16.h>
#include <cstdint>

typedef unsigned long long ull;

// Problem constants (fixed shapes)
#define BB   64
#define TT   256
#define VV   10000
#define VPAD 10240
#define EE   100
#define HH   128
#define GG   512          // 4H
#define BT   (BB*TT)      // 16384
#define KSPLIT 256        // A: [h_hi | h_lo] fp16
#define WKS   128         // B: W_fc fp16 (single copy; shared by hi & lo MMAs)

#define LOGITS_ELEMS ((size_t)BT * VV)          // 163,840,000
#define HF_OFF  LOGITS_ELEMS
#define CF_OFF  (LOGITS_ELEMS + (size_t)BB*HH)
#define FULL_OUT (LOGITS_ELEMS + 2ull*BB*HH)

// Scratch (device globals; allocation-free per harness rules)
__device__ float  g_xproj[(size_t)BT * GG];          // 33.5 MB
__device__ __half g_hs_split[(size_t)BT * KSPLIT];   // 8.4 MB  [bt][hi|lo]
__device__ __half g_wfc_split[(size_t)VPAD * WKS];   // 2.6 MB  [v][hi]

// ---------------------------------------------------------------------------
// Helpers
// ---------------------------------------------------------------------------
__device__ __forceinline__ uint32_t smem_u32(const void* p) {
    uint32_t a;
    asm("{ .reg .u64 t; cvta.to.shared.u64 t, %1; cvt.u32.u64 %0, t; }" : "=r"(a) : "l"(p));
    return a;
}
__device__ __forceinline__ void cp16(uint32_t dst, const void* src) {
    asm volatile("cp.async.cg.shared.global [%0], [%1], 16;" :: "r"(dst), "l"(src));
}
#define CP_COMMIT() asm volatile("cp.async.commit_group;" ::: "memory")
#define CP_WAIT(n)  asm volatile("cp.async.wait_group %0;" :: "n"(n) : "memory")

__device__ __forceinline__ void ldm4(uint32_t* r, uint32_t addr) {
    asm volatile("ldmatrix.sync.aligned.m8n8.x4.shared.b16 {%0,%1,%2,%3}, [%4];"
                 : "=r"(r[0]), "=r"(r[1]), "=r"(r[2]), "=r"(r[3]) : "r"(addr));
}
__device__ __forceinline__ void mma16816(float* c, const uint32_t* a,
                                         uint32_t b0, uint32_t b1) {
    asm volatile(
        "mma.sync.aligned.m16n8k16.row.col.f32.f16.f16.f32 "
        "{%0,%1,%2,%3}, {%4,%5,%6,%7}, {%8,%9}, {%0,%1,%2,%3};"
        : "+f"(c[0]), "+f"(c[1]), "+f"(c[2]), "+f"(c[3])
        : "r"(a[0]), "r"(a[1]), "r"(a[2]), "r"(a[3]), "r"(b0), "r"(b1));
}
__device__ __forceinline__ ull fma2_(ull a, ull b, ull c) {
    ull d;
    asm("fma.rn.f32x2 %0, %1, %2, %3;" : "=l"(d) : "l"(a), "l"(b), "l"(c));
    return d;
}
__device__ __forceinline__ void unpack2_(ull v, float& x, float& y) {
    asm("mov.b64 {%0, %1}, %2;" : "=f"(x), "=f"(y) : "l"(v));
}

// Fast, saturation-safe activations (MUFU EX2 based)
__device__ __forceinline__ float sigm_fast(float x) {
    return 1.f / (1.f + __expf(-x));
}
__device__ __forceinline__ float tanh_fast(float x) {
    return 2.f / (1.f + __expf(-2.f * x)) - 1.f;
}

// ---------------------------------------------------------------------------
// Kernel 1: embedding gather + input projection.
// 256 threads, each owns TWO gate rows (g, g+256).
// ---------------------------------------------------------------------------
__global__ __launch_bounds__(256) void k_embed_proj(
    const int* __restrict__ x, const float* __restrict__ emb,
    const float* __restrict__ W_ih, const float* __restrict__ b_ih,
    const float* __restrict__ b_hh)
{
    __shared__ float4 xe_s[16][25];          // 16 rows x 100 floats
    __shared__ int    toks[16];
    const int bt0 = blockIdx.x * 16;
    const int tid = threadIdx.x;

    if (tid < 16) toks[tid] = x[bt0 + tid];
    __syncthreads();
    for (int i = tid; i < 16 * 25; i += 256) {
        int r = i / 25, e4 = i - r * 25;
        xe_s[r][e4] = *reinterpret_cast<const float4*>(emb + (size_t)toks[r] * EE + 4 * e4);
    }
    __syncthreads();

    const int g0 = tid;
    const int g1 = tid + 256;
    float acc0[16], acc1[16];
#pragma unroll
    for (int r = 0; r < 16; r++) { acc0[r] = 0.f; acc1[r] = 0.f; }

    const float4* W0 = reinterpret_cast<const float4*>(W_ih + (size_t)g0 * EE);
    const float4* W1 = reinterpret_cast<const float4*>(W_ih + (size_t)g1 * EE);
    float4 w0 = W0[0], w1 = W1[0];

    for (int e4 = 0; e4 < 25; e4++) {
        const float4 w0c = w0, w1c = w1;
        if (e4 + 1 < 25) { w0 = W0[e4 + 1]; w1 = W1[e4 + 1]; }   // prefetch
#pragma unroll
        for (int r = 0; r < 16; r++) {
            const float4 v = xe_s[r][e4];    // LDS.128 broadcast
            acc0[r] += w0c.x * v.x; acc1[r] += w1c.x * v.x;
            acc0[r] += w0c.y * v.y; acc1[r] += w1c.y * v.y;
            acc0[r] += w0c.z * v.z; acc1[r] += w1c.z * v.z;
            acc0[r] += w0c.w * v.w; acc1[r] += w1c.w * v.w;
        }
    }
    const float bias0 = b_ih[g0] + b_hh[g0];
    const float bias1 = b_ih[g1] + b_hh[g1];
#pragma unroll
    for (int r = 0; r < 16; r++) {
        g_xproj[(size_t)(bt0 + r) * GG + g0] = acc0[r] + bias0;
        g_xproj[(size_t)(bt0 + r) * GG + g1] = acc1[r] + bias1;
    }
}

// ---------------------------------------------------------------------------
// Kernel 2: LSTM recurrence, ONE barrier per step, shfl gate combine.
// Thread map: q = tid&3 (gate), j = tid>>2 (unit); gate row = q*128+j.
// W-smem stored in THREAD-SLOT order (slot s holds row (s&3)*128+(s>>2)) so
// the mainloop LDS.128 Wt4_s[(jj<<9)+tid] is consecutive per warp —
// conflict-free (the R13 row-indexed layout caused 4-way conflicts).
// h double-buffered; single __syncthreads per step.
// ---------------------------------------------------------------------------
#define KREG  96
#define SMEM2_BYTES (8*512*16 + 2*HH*4)

__global__ __launch_bounds__(512, 1) void k_lstm(
    const float* __restrict__ W_hh, float* __restrict__ out, long long out_size)
{
    extern __shared__ char smem2raw[];
    ulonglong2* Wt4_s = reinterpret_cast<ulonglong2*>(smem2raw);        // [8][512]
    float*      h_s0  = reinterpret_cast<float*>(smem2raw + 8*512*16);  // [128]
    float*      h_s1  = h_s0 + HH;                                      // [128]

    const int b   = blockIdx.x;
    const int tid = threadIdx.x;
    const int q   = tid & 3;                // gate: 0=i 1=f 2=g 3=o
    const int j   = tid >> 2;               // hidden unit 0..127
    const int row = q * HH + j;             // W_hh / gate row 0..511

    ull wr2[KREG / 2];
    {
        const ulonglong2* Wg = reinterpret_cast<const ulonglong2*>(W_hh + (size_t)row * HH);
#pragma unroll
        for (int i = 0; i < KREG / 4; i++) {
            ulonglong2 u = Wg[i];
            wr2[2 * i]     = u.x;
            wr2[2 * i + 1] = u.y;
        }
    }
    // Fill W-smem in thread-slot order: slot s <- W row (s&3)*128 + (s>>2)
    for (int idx = tid; idx < 8 * 512; idx += 512) {
        int jj   = idx >> 9;
        int slot = idx & 511;
        int srow = (slot & 3) * HH + (slot >> 2);
        float4 w4 = *reinterpret_cast<const float4*>(W_hh + (size_t)srow * HH + KREG + 4 * jj);
        Wt4_s[idx] = *reinterpret_cast<ulonglong2*>(&w4);
    }
    float c = 0.f;                           // replicated across the 4 gate lanes
    if (tid < HH) { h_s0[tid] = 0.f; h_s1[tid] = 0.f; }
    __syncthreads();

    const float* xp = g_xproj + (size_t)b * TT * GG;
    float xnext = xp[row];                   // prefetch t=0
    float hlast = 0.f;

    for (int t = 0; t < TT; t++) {
        const float* hbuf = (t & 1) ? h_s1 : h_s0;
        float*       hnew = (t & 1) ? h_s0 : h_s1;
        const ulonglong2* h2q = reinterpret_cast<const ulonglong2*>(hbuf);

        const float accx = xnext;
        if (t + 1 < TT) xnext = __ldg(xp + (t + 1) * GG + row);

        ull acc2a = 0ull, acc2b = 0ull;
#pragma unroll
        for (int k4 = 0; k4 < KREG / 4; k4++) {
            ulonglong2 hp = h2q[k4];         // LDS.128 broadcast
            acc2a = fma2_(wr2[2 * k4],     hp.x, acc2a);
            acc2b = fma2_(wr2[2 * k4 + 1], hp.y, acc2b);
        }
#pragma unroll
        for (int jj = 0; jj < 8; jj++) {
            ulonglong2 hp = h2q[KREG / 4 + jj];
            ulonglong2 wv = Wt4_s[(jj << 9) + tid];   // thread-slot order: conflict-free
            acc2a = fma2_(wv.x, hp.x, acc2a);
            acc2b = fma2_(wv.y, hp.y, acc2b);
        }
        float l0, h0, l1, h1;
        unpack2_(acc2a, l0, h0);
        unpack2_(acc2b, l1, h1);
        const float gv = accx + ((l0 + l1) + (h0 + h1));

        const float v  = (q == 2) ? tanh_fast(gv) : sigm_fast(gv);
        const float a1 = __shfl_xor_sync(0xFFFFFFFFu, v, 1);
        const float a2 = __shfl_xor_sync(0xFFFFFFFFu, v, 2);
        const float a3 = __shfl_xor_sync(0xFFFFFFFFu, v, 3);
        const float ig = (q == 0) ? v  : (q == 1) ? a1 : (q == 2) ? a2 : a3;
        const float fg = (q == 0) ? a1 : (q == 1) ? v  : (q == 2) ? a3 : a2;
        const float gg = (q == 0) ? a2 : (q == 1) ? a3 : (q == 2) ? v  : a1;
        const float og = (q == 0) ? a3 : (q == 1) ? a2 : (q == 2) ? a1 : v;

        c = fg * c + ig * gg;
        const float h = og * tanh_fast(c);
        hlast = h;

        if (q == 0) {
            hnew[j] = h;
            __half hh = __float2half_rn(h);
            float  hl = h - __half2float(hh);
            size_t base = ((size_t)b * TT + t) * KSPLIT;
            g_hs_split[base + j]       = hh;
            g_hs_split[base + 128 + j] = __float2half_rn(hl);
        }
        __syncthreads();                     // hnew visible; nobody runs ahead
    }

    if (q == 0 && out_size >= (long long)FULL_OUT) {
        out[HF_OFF + (size_t)b * HH + j] = hlast;
        out[CF_OFF + (size_t)b * HH + j] = c;
    }
}

// ---------------------------------------------------------------------------
// Kernel 2b: W_fc -> fp16, single copy, zero-padded to VPAD rows
// ---------------------------------------------------------------------------
__global__ __launch_bounds__(256) void k_split_wfc(const float* __restrict__ W_fc)
{
    size_t i = (size_t)blockIdx.x * 256 + threadIdx.x;   // over VPAD*128
    int v = (int)(i >> 7);
    float w = (v < VV) ? W_fc[i] : 0.f;
    g_wfc_split[i] = __float2half_rn(w);
}

// ---------------------------------------------------------------------------
// Kernel 3: logits GEMM via mma.sync. fp16 2-term with shared B, full-K
// resident (96KB), single barrier. 8 warps as 2(m) x 4(n); warp tile 64x32.
// ---------------------------------------------------------------------------
#define SMEM3_BYTES (96 * 1024)

__global__ __launch_bounds__(256, 2) void k_logits_mma(
    const float* __restrict__ b_fc, float* __restrict__ out)
{
    extern __shared__ char smem3[];
    const uint32_t smem_base = smem_u32(smem3);
    const int tid = threadIdx.x;
    const int wid = tid >> 5;
    const int l   = tid & 31;
    const int v0  = blockIdx.x * 128;
    const int bt0 = blockIdx.y * 128;

    const __half* asrc = g_hs_split + (size_t)bt0 * KSPLIT;
    const __half* bsrc = g_wfc_split + (size_t)v0 * WKS;

    const int AHI = 0, ALO = 32768, BBF = 65536;

#pragma unroll
    for (int it = 0; it < 8; it++) {
        int i = tid + it * 256;              // 0..2047
        int row = i >> 4;
        int j   = i & 15;
        uint32_t off = (uint32_t)row * 256 + ((j >> 3) << 7) + (((j & 7) ^ (row & 7)) << 4);
        cp16(smem_base + AHI + off, asrc + (size_t)row * KSPLIT + j * 8);
        cp16(smem_base + ALO + off, asrc + (size_t)row * KSPLIT + 128 + j * 8);
        cp16(smem_base + BBF + off, bsrc + (size_t)row * WKS + j * 8);
    }
    CP_COMMIT();

    const int wm = (wid >> 2) * 64;   // warp m offset (0/64)
    const int wn = (wid & 3) * 32;    // warp n offset (0..96)

    float c[4][4][4];
#pragma unroll
    for (int mi = 0; mi < 4; mi++)
#pragma unroll
        for (int nj = 0; nj < 4; nj++)
#pragma unroll
            for (int qq = 0; qq < 4; qq++) c[mi][nj][qq] = 0.f;

    const int lrow = l & 15;
    const int lsel = l >> 4;

    CP_WAIT(0);
    __syncthreads();                  // only barrier in the whole kernel

#pragma unroll
    for (int k16 = 0; k16 < 8; k16++) {
        const int jj = 2 * k16 + lsel;               // 0..15
        const uint32_t joff = ((jj >> 3) << 7) + (((jj & 7) ^ (lrow & 7)) << 4);

        uint32_t bfr[2][4];
#pragma unroll
        for (int njp = 0; njp < 2; njp++) {
            int r = wn + njp * 16 + lrow;
            ldm4(bfr[njp], smem_base + BBF + (uint32_t)r * 256 + joff);
        }
        uint32_t a[4][4];
#pragma unroll
        for (int mi = 0; mi < 4; mi++) {
            int r = wm + mi * 16 + lrow;
            ldm4(a[mi], smem_base + AHI + (uint32_t)r * 256 + joff);
        }
#pragma unroll
        for (int mi = 0; mi < 4; mi++) {
#pragma unroll
            for (int njp = 0; njp < 2; njp++) {
                mma16816(c[mi][njp * 2 + 0], a[mi], bfr[njp][0], bfr[njp][2]);
                mma16816(c[mi][njp * 2 + 1], a[mi], bfr[njp][1], bfr[njp][3]);
            }
        }
        uint32_t alo[4][4];
#pragma unroll
        for (int mi = 0; mi < 4; mi++) {
            int r = wm + mi * 16 + lrow;
            ldm4(alo[mi], smem_base + ALO + (uint32_t)r * 256 + joff);
        }
#pragma unroll
        for (int mi = 0; mi < 4; mi++) {
#pragma unroll
            for (int njp = 0; njp < 2; njp++) {
                mma16816(c[mi][njp * 2 + 0], alo[mi], bfr[njp][0], bfr[njp][2]);
                mma16816(c[mi][njp * 2 + 1], alo[mi], bfr[njp][1], bfr[njp][3]);
            }
        }
    }

    // Epilogue: bias + guarded float2 stores
    const int g  = l >> 2;
    const int qq = l & 3;
    const int mB = bt0 + wm;
    const int nB = v0 + wn;

#pragma unroll
    for (int nj = 0; nj < 4; nj++) {
        const int v = nB + nj * 8 + 2 * qq;
        if (v >= VV) continue;
        const float2 bias = *reinterpret_cast<const float2*>(b_fc + v);
#pragma unroll
        for (int mi = 0; mi < 4; mi++) {
            const float* cc = c[mi][nj];
            const int r0 = mB + mi * 16 + g;
            float2 o0 = make_float2(cc[0] + bias.x, cc[1] + bias.y);
            float2 o1 = make_float2(cc[2] + bias.x, cc[3] + bias.y);
            *reinterpret_cast<float2*>(out + (size_t)r0 * VV + v)       = o0;
            *reinterpret_cast<float2*>(out + (size_t)(r0 + 8) * VV + v) = o1;
        }
    }
}

// ---------------------------------------------------------------------------
extern "C" void kernel_launch(void* const* d_in, const int* in_sizes, int n_in,
                              void* d_out, int out_size)
{
    const int*   x    = (const int*)  d_in[0];
    const float* emb  = (const float*)d_in[1];
    const float* W_ih = (const float*)d_in[2];
    const float* W_hh = (const float*)d_in[3];
    const float* b_ih = (const float*)d_in[4];
    const float* b_hh = (const float*)d_in[5];
    const float* W_fc = (const float*)d_in[6];
    const float* b_fc = (const float*)d_in[7];
    float* out = (float*)d_out;

    cudaFuncSetAttribute(k_lstm,       cudaFuncAttributeMaxDynamicSharedMemorySize, SMEM2_BYTES);
    cudaFuncSetAttribute(k_logits_mma, cudaFuncAttributeMaxDynamicSharedMemorySize, SMEM3_BYTES);

    // 1) embedding + input projection
    k_embed_proj<<<BT / 16, 256>>>(x, emb, W_ih, b_ih, b_hh);

    // 1b) W_fc fp16 prep (independent of 1/2)
    k_split_wfc<<<(VPAD * WKS) / 256, 256>>>(W_fc);

    // 2) recurrence (writes hs split + h_n/c_n tail of out)
    k_lstm<<<BB, 512, SMEM2_BYTES>>>(W_hh, out, (long long)out_size);

    // 3) logits GEMM on HMMA tensor cores
    dim3 g3(VPAD / 128, BT / 128);
    k_logits_mma<<<g3, 256, SMEM3_BYTES>>>(b_fc, out);
}

// round 15
// speedup vs baseline: 1.4368x; 1.0951x over previous
#include <cuda_runtime.h>
#include <cuda_bf16.h>
#include <cuda_fp16.h>
#include <cstdint>

typedef unsigned long long ull;

// Problem constants (fixed shapes)
#define BB   64
#define TT   256
#define VV   10000
#define VPAD 10240
#define EE   100
#define HH   128
#define GG   512          // 4H
#define BT   (BB*TT)      // 16384
#define KSPLIT 256        // A: [h_hi | h_lo] fp16
#define WKS   128         // B: W_fc fp16 (single copy; shared by hi & lo MMAs)

#define LOGITS_ELEMS ((size_t)BT * VV)          // 163,840,000
#define HF_OFF  LOGITS_ELEMS
#define CF_OFF  (LOGITS_ELEMS + (size_t)BB*HH)
#define FULL_OUT (LOGITS_ELEMS + 2ull*BB*HH)

// Scratch (device globals; allocation-free per harness rules)
__device__ float  g_xproj[(size_t)BT * GG];          // 33.5 MB
__device__ __half g_hs_split[(size_t)BT * KSPLIT];   // 8.4 MB  [bt][hi|lo]
__device__ __half g_wfc_split[(size_t)VPAD * WKS];   // 2.6 MB  [v][hi]

// ---------------------------------------------------------------------------
// Helpers
// ---------------------------------------------------------------------------
__device__ __forceinline__ uint32_t smem_u32(const void* p) {
    uint32_t a;
    asm("{ .reg .u64 t; cvta.to.shared.u64 t, %1; cvt.u32.u64 %0, t; }" : "=r"(a) : "l"(p));
    return a;
}
__device__ __forceinline__ void cp16(uint32_t dst, const void* src) {
    asm volatile("cp.async.cg.shared.global [%0], [%1], 16;" :: "r"(dst), "l"(src));
}
#define CP_COMMIT() asm volatile("cp.async.commit_group;" ::: "memory")
#define CP_WAIT(n)  asm volatile("cp.async.wait_group %0;" :: "n"(n) : "memory")

__device__ __forceinline__ void ldm4(uint32_t* r, uint32_t addr) {
    asm volatile("ldmatrix.sync.aligned.m8n8.x4.shared.b16 {%0,%1,%2,%3}, [%4];"
                 : "=r"(r[0]), "=r"(r[1]), "=r"(r[2]), "=r"(r[3]) : "r"(addr));
}
__device__ __forceinline__ void mma16816(float* c, const uint32_t* a,
                                         uint32_t b0, uint32_t b1) {
    asm volatile(
        "mma.sync.aligned.m16n8k16.row.col.f32.f16.f16.f32 "
        "{%0,%1,%2,%3}, {%4,%5,%6,%7}, {%8,%9}, {%0,%1,%2,%3};"
        : "+f"(c[0]), "+f"(c[1]), "+f"(c[2]), "+f"(c[3])
        : "r"(a[0]), "r"(a[1]), "r"(a[2]), "r"(a[3]), "r"(b0), "r"(b1));
}
__device__ __forceinline__ ull fma2_(ull a, ull b, ull c) {
    ull d;
    asm("fma.rn.f32x2 %0, %1, %2, %3;" : "=l"(d) : "l"(a), "l"(b), "l"(c));
    return d;
}
__device__ __forceinline__ void unpack2_(ull v, float& x, float& y) {
    asm("mov.b64 {%0, %1}, %2;" : "=f"(x), "=f"(y) : "l"(v));
}

// Fast, saturation-safe activations (MUFU EX2 based)
__device__ __forceinline__ float sigm_fast(float x) {
    return 1.f / (1.f + __expf(-x));
}
__device__ __forceinline__ float tanh_fast(float x) {
    return 2.f / (1.f + __expf(-2.f * x)) - 1.f;
}

// ---------------------------------------------------------------------------
// Kernel 1: embedding gather + input projection.
// 256 threads, each owns TWO gate rows (g, g+256).
// ---------------------------------------------------------------------------
__global__ __launch_bounds__(256) void k_embed_proj(
    const int* __restrict__ x, const float* __restrict__ emb,
    const float* __restrict__ W_ih, const float* __restrict__ b_ih,
    const float* __restrict__ b_hh)
{
    __shared__ float4 xe_s[16][25];          // 16 rows x 100 floats
    __shared__ int    toks[16];
    const int bt0 = blockIdx.x * 16;
    const int tid = threadIdx.x;

    if (tid < 16) toks[tid] = x[bt0 + tid];
    __syncthreads();
    for (int i = tid; i < 16 * 25; i += 256) {
        int r = i / 25, e4 = i - r * 25;
        xe_s[r][e4] = *reinterpret_cast<const float4*>(emb + (size_t)toks[r] * EE + 4 * e4);
    }
    __syncthreads();

    const int g0 = tid;
    const int g1 = tid + 256;
    float acc0[16], acc1[16];
#pragma unroll
    for (int r = 0; r < 16; r++) { acc0[r] = 0.f; acc1[r] = 0.f; }

    const float4* W0 = reinterpret_cast<const float4*>(W_ih + (size_t)g0 * EE);
    const float4* W1 = reinterpret_cast<const float4*>(W_ih + (size_t)g1 * EE);
    float4 w0 = W0[0], w1 = W1[0];

    for (int e4 = 0; e4 < 25; e4++) {
        const float4 w0c = w0, w1c = w1;
        if (e4 + 1 < 25) { w0 = W0[e4 + 1]; w1 = W1[e4 + 1]; }   // prefetch
#pragma unroll
        for (int r = 0; r < 16; r++) {
            const float4 v = xe_s[r][e4];    // LDS.128 broadcast
            acc0[r] += w0c.x * v.x; acc1[r] += w1c.x * v.x;
            acc0[r] += w0c.y * v.y; acc1[r] += w1c.y * v.y;
            acc0[r] += w0c.z * v.z; acc1[r] += w1c.z * v.z;
            acc0[r] += w0c.w * v.w; acc1[r] += w1c.w * v.w;
        }
    }
    const float bias0 = b_ih[g0] + b_hh[g0];
    const float bias1 = b_ih[g1] + b_hh[g1];
#pragma unroll
    for (int r = 0; r < 16; r++) {
        g_xproj[(size_t)(bt0 + r) * GG + g0] = acc0[r] + bias0;
        g_xproj[(size_t)(bt0 + r) * GG + g1] = acc1[r] + bias1;
    }
}

// ---------------------------------------------------------------------------
// Kernel 2: LSTM recurrence (R12-proven version, 273us).
// 512 threads; W k=0..95 in regs (f32x2), k=96..127 in SMEM pair-quads.
// All-thread combine with replicated c; two barriers/step.
// ---------------------------------------------------------------------------
#define KREG  96
#define KSMEM 32
#define SMEM2_BYTES (8*512*16 + (HH + GG) * 4)

__global__ __launch_bounds__(512, 1) void k_lstm(
    const float* __restrict__ W_hh, float* __restrict__ out, long long out_size)
{
    extern __shared__ char smem2raw[];
    ulonglong2* Wt4_s  = reinterpret_cast<ulonglong2*>(smem2raw);      // [8][512]
    float*      h_s    = reinterpret_cast<float*>(smem2raw + 8*512*16); // [128]
    float*      gates_s= h_s + HH;                                      // [512]

    const int b   = blockIdx.x;
    const int tid = threadIdx.x;
    const int q   = tid >> 7;               // gate quarter: 0=i 1=f 2=g 3=o
    const int j   = tid & 127;              // hidden unit owned in combine

    ull wr2[KREG / 2];
    {
        const ulonglong2* Wg = reinterpret_cast<const ulonglong2*>(W_hh + (size_t)tid * HH);
#pragma unroll
        for (int i = 0; i < KREG / 4; i++) {
            ulonglong2 u = Wg[i];
            wr2[2 * i]     = u.x;
            wr2[2 * i + 1] = u.y;
        }
    }
    for (int idx = tid; idx < 8 * 512; idx += 512) {
        int jj = idx >> 9;
        int g2 = idx & 511;
        float4 w4 = *reinterpret_cast<const float4*>(W_hh + (size_t)g2 * HH + KREG + 4 * jj);
        Wt4_s[idx] = *reinterpret_cast<ulonglong2*>(&w4);
    }
    float c = 0.f;                           // replicated 4x across gate quarters
    if (tid < HH) h_s[tid] = 0.f;
    __syncthreads();

    const float* xp = g_xproj + (size_t)b * TT * GG;
    const ulonglong2* h2q = reinterpret_cast<const ulonglong2*>(h_s);

    float xnext = xp[tid];                   // prefetch t=0

    for (int t = 0; t < TT; t++) {
        const float accx = xnext;
        if (t + 1 < TT) xnext = __ldg(xp + (t + 1) * GG + tid);

        ull acc2a = 0ull, acc2b = 0ull;
#pragma unroll
        for (int k4 = 0; k4 < KREG / 4; k4++) {
            ulonglong2 hp = h2q[k4];         // LDS.128 broadcast
            acc2a = fma2_(wr2[2 * k4],     hp.x, acc2a);
            acc2b = fma2_(wr2[2 * k4 + 1], hp.y, acc2b);
        }
#pragma unroll
        for (int jj = 0; jj < 8; jj++) {
            ulonglong2 hp = h2q[KREG / 4 + jj];
            ulonglong2 wv = Wt4_s[(jj << 9) + tid];
            acc2a = fma2_(wv.x, hp.x, acc2a);
            acc2b = fma2_(wv.y, hp.y, acc2b);
        }
        float l0, h0, l1, h1;
        unpack2_(acc2a, l0, h0);
        unpack2_(acc2b, l1, h1);
        const float gv = accx + ((l0 + l1) + (h0 + h1));

        gates_s[tid] = (q == 2) ? tanh_fast(gv) : sigm_fast(gv);
        __syncthreads();

        // All threads combine (c replicated; deterministic identical updates)
        {
            float ig = gates_s[j];
            float fg = gates_s[HH + j];
            float gg = gates_s[2 * HH + j];
            float og = gates_s[3 * HH + j];
            c = fg * c + ig * gg;
            float h = og * tanh_fast(c);
            if (tid < HH) {
                h_s[j] = h;
                __half hh = __float2half_rn(h);
                float  hl = h - __half2float(hh);
                size_t base = ((size_t)b * TT + t) * KSPLIT;
                g_hs_split[base + j]       = hh;
                g_hs_split[base + 128 + j] = __float2half_rn(hl);
            }
        }
        __syncthreads();
    }

    if (tid < HH && out_size >= (long long)FULL_OUT) {
        out[HF_OFF + (size_t)b * HH + tid] = h_s[tid];
        out[CF_OFF + (size_t)b * HH + tid] = c;
    }
}

// ---------------------------------------------------------------------------
// Kernel 2b: W_fc -> fp16, single copy, zero-padded to VPAD rows
// ---------------------------------------------------------------------------
__global__ __launch_bounds__(256) void k_split_wfc(const float* __restrict__ W_fc)
{
    size_t i = (size_t)blockIdx.x * 256 + threadIdx.x;   // over VPAD*128
    int v = (int)(i >> 7);
    float w = (v < VV) ? W_fc[i] : 0.f;
    g_wfc_split[i] = __float2half_rn(w);
}

// ---------------------------------------------------------------------------
// Kernel 3: logits GEMM via mma.sync. fp16 2-term with shared B, full-K
// resident (96KB), single barrier. 8 warps as 4(m) x 2(n); warp tile 32x64:
// per k16 only 8 ldm4 (A hi 2 + A lo 2 + B 4) feed 32 MMAs (was 10).
// ---------------------------------------------------------------------------
#define SMEM3_BYTES (96 * 1024)

__global__ __launch_bounds__(256, 2) void k_logits_mma(
    const float* __restrict__ b_fc, float* __restrict__ out)
{
    extern __shared__ char smem3[];
    const uint32_t smem_base = smem_u32(smem3);
    const int tid = threadIdx.x;
    const int wid = tid >> 5;
    const int l   = tid & 31;
    const int v0  = blockIdx.x * 128;
    const int bt0 = blockIdx.y * 128;

    const __half* asrc = g_hs_split + (size_t)bt0 * KSPLIT;
    const __half* bsrc = g_wfc_split + (size_t)v0 * WKS;

    const int AHI = 0, ALO = 32768, BBF = 65536;

#pragma unroll
    for (int it = 0; it < 8; it++) {
        int i = tid + it * 256;              // 0..2047
        int row = i >> 4;
        int j   = i & 15;
        uint32_t off = (uint32_t)row * 256 + ((j >> 3) << 7) + (((j & 7) ^ (row & 7)) << 4);
        cp16(smem_base + AHI + off, asrc + (size_t)row * KSPLIT + j * 8);
        cp16(smem_base + ALO + off, asrc + (size_t)row * KSPLIT + 128 + j * 8);
        cp16(smem_base + BBF + off, bsrc + (size_t)row * WKS + j * 8);
    }
    CP_COMMIT();

    const int wm = (wid & 3) * 32;    // warp m offset (0/32/64/96)
    const int wn = (wid >> 2) * 64;   // warp n offset (0/64)

    float c[2][8][4];
#pragma unroll
    for (int mi = 0; mi < 2; mi++)
#pragma unroll
        for (int nj = 0; nj < 8; nj++)
#pragma unroll
            for (int qq = 0; qq < 4; qq++) c[mi][nj][qq] = 0.f;

    const int lrow = l & 15;
    const int lsel = l >> 4;

    CP_WAIT(0);
    __syncthreads();                  // only barrier in the whole kernel

#pragma unroll
    for (int k16 = 0; k16 < 8; k16++) {
        const int jj = 2 * k16 + lsel;               // 0..15
        const uint32_t joff = ((jj >> 3) << 7) + (((jj & 7) ^ (lrow & 7)) << 4);

        uint32_t bfr[4][4];
#pragma unroll
        for (int njp = 0; njp < 4; njp++) {
            int r = wn + njp * 16 + lrow;
            ldm4(bfr[njp], smem_base + BBF + (uint32_t)r * 256 + joff);
        }
        uint32_t a[2][4];
#pragma unroll
        for (int mi = 0; mi < 2; mi++) {
            int r = wm + mi * 16 + lrow;
            ldm4(a[mi], smem_base + AHI + (uint32_t)r * 256 + joff);
        }
#pragma unroll
        for (int mi = 0; mi < 2; mi++) {
#pragma unroll
            for (int njp = 0; njp < 4; njp++) {
                mma16816(c[mi][njp * 2 + 0], a[mi], bfr[njp][0], bfr[njp][2]);
                mma16816(c[mi][njp * 2 + 1], a[mi], bfr[njp][1], bfr[njp][3]);
            }
        }
        uint32_t alo[2][4];
#pragma unroll
        for (int mi = 0; mi < 2; mi++) {
            int r = wm + mi * 16 + lrow;
            ldm4(alo[mi], smem_base + ALO + (uint32_t)r * 256 + joff);
        }
#pragma unroll
        for (int mi = 0; mi < 2; mi++) {
#pragma unroll
            for (int njp = 0; njp < 4; njp++) {
                mma16816(c[mi][njp * 2 + 0], alo[mi], bfr[njp][0], bfr[njp][2]);
                mma16816(c[mi][njp * 2 + 1], alo[mi], bfr[njp][1], bfr[njp][3]);
            }
        }
    }

    // Epilogue: bias + guarded float2 stores
    const int g  = l >> 2;
    const int qq = l & 3;
    const int mB = bt0 + wm;
    const int nB = v0 + wn;

#pragma unroll
    for (int nj = 0; nj < 8; nj++) {
        const int v = nB + nj * 8 + 2 * qq;
        if (v >= VV) continue;
        const float2 bias = *reinterpret_cast<const float2*>(b_fc + v);
#pragma unroll
        for (int mi = 0; mi < 2; mi++) {
            const float* cc = c[mi][nj];
            const int r0 = mB + mi * 16 + g;
            float2 o0 = make_float2(cc[0] + bias.x, cc[1] + bias.y);
            float2 o1 = make_float2(cc[2] + bias.x, cc[3] + bias.y);
            *reinterpret_cast<float2*>(out + (size_t)r0 * VV + v)       = o0;
            *reinterpret_cast<float2*>(out + (size_t)(r0 + 8) * VV + v) = o1;
        }
    }
}

// ---------------------------------------------------------------------------
extern "C" void kernel_launch(void* const* d_in, const int* in_sizes, int n_in,
                              void* d_out, int out_size)
{
    const int*   x    = (const int*)  d_in[0];
    const float* emb  = (const float*)d_in[1];
    const float* W_ih = (const float*)d_in[2];
    const float* W_hh = (const float*)d_in[3];
    const float* b_ih = (const float*)d_in[4];
    const float* b_hh = (const float*)d_in[5];
    const float* W_fc = (const float*)d_in[6];
    const float* b_fc = (const float*)d_in[7];
    float* out = (float*)d_out;

    cudaFuncSetAttribute(k_lstm,       cudaFuncAttributeMaxDynamicSharedMemorySize, SMEM2_BYTES);
    cudaFuncSetAttribute(k_logits_mma, cudaFuncAttributeMaxDynamicSharedMemorySize, SMEM3_BYTES);

    // 1) embedding + input projection
    k_embed_proj<<<BT / 16, 256>>>(x, emb, W_ih, b_ih, b_hh);

    // 1b) W_fc fp16 prep (independent of 1/2)
    k_split_wfc<<<(VPAD * WKS) / 256, 256>>>(W_fc);

    // 2) recurrence (writes hs split + h_n/c_n tail of out)
    k_lstm<<<BB, 512, SMEM2_BYTES>>>(W_hh, out, (long long)out_size);

    // 3) logits GEMM on HMMA tensor cores
    dim3 g3(VPAD / 128, BT / 128);
    k_logits_mma<<<g3, 256, SMEM3_BYTES>>>(b_fc, out);
}